// round 3
// baseline (speedup 1.0000x reference)
#include <cuda_runtime.h>
#include <math.h>

// ---------------------------------------------------------------------------
// Shifted-window attention (FA), fully fused: one CTA per 8x8 window.
// x: [4,256,256,224] fp32.  4096 windows, 64 tokens, 8 heads, dh=28.
// ---------------------------------------------------------------------------

__device__ __forceinline__ unsigned long long pk2(float lo, float hi) {
    unsigned long long r;
    asm("mov.b64 %0, {%1, %2};" : "=l"(r) : "f"(lo), "f"(hi));
    return r;
}
__device__ __forceinline__ void upk2(unsigned long long v, float& lo, float& hi) {
    asm("mov.b64 {%0, %1}, %2;" : "=f"(lo), "=f"(hi) : "l"(v));
}
__device__ __forceinline__ void ffma2(unsigned long long& d,
                                      unsigned long long a,
                                      unsigned long long b) {
    // packed 2x fp32 FMA (Blackwell FFMA2) — ptxas never emits this from C++
    asm("fma.rn.f32x2 %0, %1, %2, %0;" : "+l"(d) : "l"(a), "l"(b));
}

// smem layout constants (floats)
#define XPAD 228   // xw / o accumulator row pitch (kills 224%32==0 conflicts)
#define QP   86    // qkv row pitch (even -> 8B-aligned v pairs, 86%32=22)
#define SP   65    // sim row pitch (odd -> conflict-free)

__global__ void __launch_bounds__(256, 1)
fa_window_kernel(const float* __restrict__ x,
                 const float* __restrict__ w_qk,
                 const float* __restrict__ w_v,
                 const float* __restrict__ w_out,
                 const float* __restrict__ b_out,
                 const float* __restrict__ pcq_w,
                 const float* __restrict__ pcq_b,
                 const float* __restrict__ pck_w,
                 const float* __restrict__ pck_b,
                 const float* __restrict__ mlp1_w,
                 const float* __restrict__ mlp2_w1,
                 const float* __restrict__ mlp2_w2,
                 float* __restrict__ out)
{
    extern __shared__ float sm[];
    float* xw  = sm;                   // [64][XPAD]   window tokens
    float* oac = xw  + 64 * XPAD;      // [64][XPAD]   per-token head-concat o
    float* qkv = oac + 64 * XPAD;      // [64][QP]     q(0..27) k(28..55) v(56..83)
    float* U   = qkv + 64 * QP;        // union: wtile [224][84] / sim [64][SP]
    float* Sq  = U   + 224 * 84;       // [64]
    float* Sk  = Sq  + 64;             // [64]
    float* t1  = Sk  + 64;             // [64]
    float* h1  = t1  + 64;             // [64]
    float* thp = h1  + 64;             // [1] theta

    const int t  = threadIdx.x;
    const int w  = blockIdx.x;
    const int bi = w >> 10;            // batch  (4)
    const int wh = (w >> 5) & 31;      // window row (32)
    const int ww = w & 31;             // window col (32)

    // ---- gather rolled window tokens: rolled[r][c] = x[(r-4)%256][(c-4)%256]
    for (int idx = t; idx < 64 * 224; idx += 256) {
        int tok = idx / 224, ch = idx - tok * 224;
        int r  = wh * 8 + (tok >> 3), c = ww * 8 + (tok & 7);
        int sr = (r + 252) & 255, sc = (c + 252) & 255;
        xw[tok * XPAD + ch] =
            x[(((size_t)(bi * 256 + sr)) * 256 + sc) * 224 + ch];
    }
    __syncthreads();

    // projection / attn-v / out-proj thread tiling: 16 token-groups x 14 col-groups
    const int gtok = t / 14;           // 0..18 (valid < 16)
    const int gcol = t - gtok * 14;    // 0..13
    const bool act = (gtok < 16);      // 224 active threads

    for (int h = 0; h < 8; ++h) {
        // ---- stage weight tile [224 x 84]: q | k | v columns of head h ----
        for (int idx = t; idx < 224 * 84; idx += 256) {
            int c = idx / 84, j = idx - c * 84;
            float wv;
            if (j < 28)      wv = w_qk[c * 448 + h * 28 + j];
            else if (j < 56) wv = w_qk[c * 448 + 224 + h * 28 + (j - 28)];
            else             wv = w_v [c * 224 + h * 28 + (j - 56)];
            U[idx] = wv;
        }
        __syncthreads();

        // ---- projection GEMM: [64 x 84] = xw[64 x 224] @ wtile, FFMA2 packed
        if (act) {
            unsigned long long acc[4][3] = {};
            const float* xr = xw + gtok * 4 * XPAD;
            const float* wc = U + gcol * 6;
            #pragma unroll 2
            for (int c = 0; c < 224; ++c) {
                float x0 = xr[c], x1 = xr[XPAD + c];
                float x2 = xr[2 * XPAD + c], x3 = xr[3 * XPAD + c];
                unsigned long long a0 = pk2(x0, x0), a1 = pk2(x1, x1);
                unsigned long long a2 = pk2(x2, x2), a3 = pk2(x3, x3);
                const unsigned long long* wp =
                    reinterpret_cast<const unsigned long long*>(wc + c * 84);
                unsigned long long w0 = wp[0], w1 = wp[1], w2 = wp[2];
                ffma2(acc[0][0], a0, w0); ffma2(acc[0][1], a0, w1); ffma2(acc[0][2], a0, w2);
                ffma2(acc[1][0], a1, w0); ffma2(acc[1][1], a1, w1); ffma2(acc[1][2], a1, w2);
                ffma2(acc[2][0], a2, w0); ffma2(acc[2][1], a2, w1); ffma2(acc[2][2], a2, w2);
                ffma2(acc[3][0], a3, w0); ffma2(acc[3][1], a3, w1); ffma2(acc[3][2], a3, w2);
            }
            #pragma unroll
            for (int u = 0; u < 4; ++u) {
                float* q = qkv + (gtok * 4 + u) * QP + gcol * 6;
                #pragma unroll
                for (int p = 0; p < 3; ++p) upk2(acc[u][p], q[2 * p], q[2 * p + 1]);
            }
        }
        __syncthreads();

        // ---- sigma scalars Sq/Sk (threads 0..63) ----
        if (t < 64) {
            const float* qr = qkv + t * QP;
            float sq = 0.f, sk = 0.f;
            #pragma unroll
            for (int d = 0; d < 28; ++d) {
                sq = fmaf(qr[d],      pcq_w[d], sq);
                sk = fmaf(qr[28 + d], pck_w[d], sk);
            }
            Sq[t] = sq + pcq_b[0];
            Sk[t] = sk + pck_b[0];
        }

        // ---- sim = q k^T  [64 x 64], 4x4 register tile per thread ----
        {
            int ig = t >> 4, jg = t & 15;
            float acc[4][4] = {};
            const float* q0 = qkv + ig * 4 * QP;
            const float* k0 = qkv + jg * 4 * QP + 28;
            #pragma unroll 4
            for (int d = 0; d < 28; ++d) {
                float qa[4], ka[4];
                #pragma unroll
                for (int u = 0; u < 4; ++u) {
                    qa[u] = q0[u * QP + d];
                    ka[u] = k0[u * QP + d];
                }
                #pragma unroll
                for (int u = 0; u < 4; ++u)
                    #pragma unroll
                    for (int v2 = 0; v2 < 4; ++v2)
                        acc[u][v2] = fmaf(qa[u], ka[v2], acc[u][v2]);
            }
            #pragma unroll
            for (int u = 0; u < 4; ++u)
                #pragma unroll
                for (int v2 = 0; v2 < 4; ++v2)
                    U[(ig * 4 + u) * SP + jg * 4 + v2] = acc[u][v2];
        }
        __syncthreads();

        // ---- learned threshold theta (from UNmodulated sim, diag removed) ----
        if (t < 64) {
            const float* sr = U + t * SP;
            float s = 0.f;
            #pragma unroll 4
            for (int j = 0; j < 64; ++j) s = fmaf(sr[j], mlp1_w[j], s);
            s -= sr[t] * mlp1_w[t];            // remove diagonal term
            t1[t] = s;
        }
        __syncthreads();
        if (t < 64) {
            float s = 0.f;
            #pragma unroll 4
            for (int j = 0; j < 64; ++j) s = fmaf(t1[j], mlp2_w1[j * 64 + t], s);
            s = (s >= 0.f) ? s : 0.1f * s;     // LeakyReLU(0.1)
            h1[t] = s * mlp2_w2[t];
        }
        __syncthreads();
        if (t == 0) {
            float s = 0.f;
            for (int i = 0; i < 64; ++i) s += h1[i];
            thp[0] = s;
        }
        __syncthreads();

        // ---- sigma modulation + row softmax + threshold gate ----
        {
            float theta = thp[0];
            int i = t >> 2, p = t & 3;         // 64 rows x 4 lanes/row (same warp quad)
            float sqi = Sq[i];
            float* srow = U + i * SP + p * 16;
            float sv[16], mx = -1e30f;
            #pragma unroll
            for (int jj = 0; jj < 16; ++jj) {
                float val = srow[jj] * (sqi * Sk[p * 16 + jj]);
                sv[jj] = val;
                mx = fmaxf(mx, val);
            }
            mx = fmaxf(mx, __shfl_xor_sync(0xffffffffu, mx, 1));
            mx = fmaxf(mx, __shfl_xor_sync(0xffffffffu, mx, 2));
            float ev[16], sum = 0.f;
            #pragma unroll
            for (int jj = 0; jj < 16; ++jj) {
                ev[jj] = __expf(sv[jj] - mx);
                sum += ev[jj];
            }
            sum += __shfl_xor_sync(0xffffffffu, sum, 1);
            sum += __shfl_xor_sync(0xffffffffu, sum, 2);
            float inv = 1.f / sum;
            #pragma unroll
            for (int jj = 0; jj < 16; ++jj)
                srow[jj] = (sv[jj] > theta) ? ev[jj] * inv : 0.f;
        }
        __syncthreads();

        // ---- o_h = attn @ v   [64 x 28] -> o accumulator column slice ----
        if (act) {
            float acc[4][2] = {};
            const float* ar = U + gtok * 4 * SP;
            const float* vb = qkv + 56 + gcol * 2;
            #pragma unroll 4
            for (int j = 0; j < 64; ++j) {
                float v0 = vb[j * QP], v1 = vb[j * QP + 1];
                #pragma unroll
                for (int u = 0; u < 4; ++u) {
                    float a = ar[u * SP + j];
                    acc[u][0] = fmaf(a, v0, acc[u][0]);
                    acc[u][1] = fmaf(a, v1, acc[u][1]);
                }
            }
            #pragma unroll
            for (int u = 0; u < 4; ++u) {
                float* op = oac + (gtok * 4 + u) * XPAD + h * 28 + gcol * 2;
                op[0] = acc[u][0];
                op[1] = acc[u][1];
            }
        }
        __syncthreads();
    } // heads

    // ---- out projection (4 chunks of 56 output cols) + un-roll scatter ----
    for (int e0 = 0; e0 < 224; e0 += 56) {
        __syncthreads();   // previous chunk GEMM done reading U
        for (int idx = t; idx < 224 * 56; idx += 256) {
            int c = idx / 56, j = idx - c * 56;
            U[idx] = w_out[c * 224 + e0 + j];
        }
        __syncthreads();
        if (act) {
            unsigned long long acc[4][2] = {};
            const float* orow = oac + gtok * 4 * XPAD;
            const float* wc = U + gcol * 4;
            #pragma unroll 2
            for (int c = 0; c < 224; ++c) {
                float x0 = orow[c], x1 = orow[XPAD + c];
                float x2 = orow[2 * XPAD + c], x3 = orow[3 * XPAD + c];
                unsigned long long a0 = pk2(x0, x0), a1 = pk2(x1, x1);
                unsigned long long a2 = pk2(x2, x2), a3 = pk2(x3, x3);
                const unsigned long long* wp =
                    reinterpret_cast<const unsigned long long*>(wc + c * 56);
                unsigned long long w0 = wp[0], w1 = wp[1];
                ffma2(acc[0][0], a0, w0); ffma2(acc[0][1], a0, w1);
                ffma2(acc[1][0], a1, w0); ffma2(acc[1][1], a1, w1);
                ffma2(acc[2][0], a2, w0); ffma2(acc[2][1], a2, w1);
                ffma2(acc[3][0], a3, w0); ffma2(acc[3][1], a3, w1);
            }
            int e = e0 + gcol * 4;
            float b0 = b_out[e], b1 = b_out[e + 1];
            float b2 = b_out[e + 2], b3 = b_out[e + 3];
            #pragma unroll
            for (int u = 0; u < 4; ++u) {
                int tok = gtok * 4 + u;
                int r  = wh * 8 + (tok >> 3), c = ww * 8 + (tok & 7);
                int fr = (r + 252) & 255, fc = (c + 252) & 255;  // un-roll (-4,-4)
                float* op = out +
                    (((size_t)(bi * 256 + fr)) * 256 + fc) * 224 + e;
                float r0, r1, r2, r3;
                upk2(acc[u][0], r0, r1);
                upk2(acc[u][1], r2, r3);
                op[0] = r0 + b0; op[1] = r1 + b1;
                op[2] = r2 + b2; op[3] = r3 + b3;
            }
        }
    }
}

// floats: 2*64*228 + 64*86 + 224*84 + 4*64 + 4 = 53764
#define FA_SMEM_BYTES (53764 * 4)

extern "C" void kernel_launch(void* const* d_in, const int* in_sizes, int n_in,
                              void* d_out, int out_size) {
    (void)in_sizes; (void)n_in; (void)out_size;
    const float* x       = (const float*)d_in[0];
    const float* w_qk    = (const float*)d_in[1];
    const float* w_v     = (const float*)d_in[2];
    const float* w_out   = (const float*)d_in[3];
    const float* b_out   = (const float*)d_in[4];
    const float* pcq_w   = (const float*)d_in[5];
    const float* pcq_b   = (const float*)d_in[6];
    const float* pck_w   = (const float*)d_in[7];
    const float* pck_b   = (const float*)d_in[8];
    const float* mlp1_w  = (const float*)d_in[9];
    const float* mlp2_w1 = (const float*)d_in[10];
    const float* mlp2_w2 = (const float*)d_in[11];
    float* out = (float*)d_out;

    cudaFuncSetAttribute(fa_window_kernel,
                         cudaFuncAttributeMaxDynamicSharedMemorySize,
                         FA_SMEM_BYTES);
    fa_window_kernel<<<4096, 256, FA_SMEM_BYTES>>>(
        x, w_qk, w_v, w_out, b_out, pcq_w, pcq_b, pck_w, pck_b,
        mlp1_w, mlp2_w1, mlp2_w2, out);
}

// round 4
// speedup vs baseline: 1.3701x; 1.3701x over previous
#include <cuda_runtime.h>
#include <math.h>

// ---------------------------------------------------------------------------
// Shifted-window attention, fused: one CTA (512 thr) per 8x8 window.
// x: [4,256,256,224] fp32.  4096 windows, 64 tokens, 8 heads, dh=28.
// Transposed smem layouts (channel-major) => LDS.128 operand loads.
// K-split across two 224-thread groups for the big GEMMs.
// ---------------------------------------------------------------------------

typedef unsigned long long ull;

__device__ __forceinline__ ull pk2(float lo, float hi) {
    ull r; asm("mov.b64 %0, {%1, %2};" : "=l"(r) : "f"(lo), "f"(hi)); return r;
}
__device__ __forceinline__ void upk2(ull v, float& lo, float& hi) {
    asm("mov.b64 {%0, %1}, %2;" : "=f"(lo), "=f"(hi) : "l"(v));
}
__device__ __forceinline__ void ffma2(ull& d, ull a, ull b) {
    // packed 2x fp32 FMA (Blackwell FFMA2) — ptxas never emits this from C++
    asm("fma.rn.f32x2 %0, %1, %2, %0;" : "+l"(d) : "l"(a), "l"(b));
}

#define TP 68   // xT / oacT row pitch (tokens), mult of 4 for LDS.128
#define QT 68   // qkvT row pitch
#define SP 68   // sim row pitch

__global__ void __launch_bounds__(512, 1)
fa_window_kernel(const float* __restrict__ x,
                 const float* __restrict__ w_qk,
                 const float* __restrict__ w_v,
                 const float* __restrict__ w_out,
                 const float* __restrict__ b_out,
                 const float* __restrict__ pcq_w,
                 const float* __restrict__ pcq_b,
                 const float* __restrict__ pck_w,
                 const float* __restrict__ pck_b,
                 const float* __restrict__ mlp1_w,
                 const float* __restrict__ mlp2_w1,
                 const float* __restrict__ mlp2_w2,
                 float* __restrict__ out)
{
    extern __shared__ float sm[];
    float* xT   = sm;                    // [224][TP]  channel-major tokens
    float* oacT = xT   + 224 * TP;       // [224][TP]  channel-major head-concat o
    float* qkvT = oacT + 224 * TP;       // [84][QT]   q(0..27) k(28..55) v(56..83), col=token
    float* U    = qkvT + 84 * QT;        // union: wtile [224][84] / sim [64][SP] / wout chunk [224][56]
    float* Sq   = U    + 224 * 84;       // [64]
    float* Sk   = Sq   + 64;             // [64]
    float* t1   = Sk   + 64;             // [64]
    float* h1   = t1   + 64;             // [64]
    float* thp  = h1   + 64;             // [1]
    float* Pbuf = qkvT;                  // [64][56] out-proj partials (qkvT dead by then)

    const int t  = threadIdx.x;
    const int w  = blockIdx.x;
    const int bi = w >> 10;              // batch (4)
    const int wh = (w >> 5) & 31;        // window row
    const int ww = w & 31;               // window col

    // ---- gather rolled window: rolled[r][c] = x[(r-4)%256][(c-4)%256] ----
    for (int idx = t; idx < 64 * 224; idx += 512) {
        int tok = idx / 224, ch = idx - tok * 224;
        int r  = wh * 8 + (tok >> 3), c = ww * 8 + (tok & 7);
        int sr = (r + 252) & 255, sc = (c + 252) & 255;
        xT[ch * TP + tok] =
            x[(((size_t)(bi * 256 + sr)) * 256 + sc) * 224 + ch];
    }
    __syncthreads();

    // GEMM thread tiling: (gtok 0..15) x (gcol 0..13) x (kh 0..1) = 448 active
    const int gcol = t % 14;
    const int gtok = (t / 14) % 16;
    const int kh   = t / 224;            // 2 => idle warps 14,15
    const bool act  = (kh < 2);
    const bool act1 = (t < 224);         // attn@v group (warps 0..6)

    for (int h = 0; h < 8; ++h) {
        // ---- stage weight tile U[224][84]: q | k | v cols of head h ----
        for (int idx = t; idx < 224 * 84; idx += 512) {
            int c = idx / 84, j = idx - c * 84;
            float wv;
            if (j < 28)      wv = w_qk[c * 448 + h * 28 + j];
            else if (j < 56) wv = w_qk[c * 448 + 224 + h * 28 + (j - 28)];
            else             wv = w_v [c * 224 + h * 28 + (j - 56)];
            U[idx] = wv;
        }
        __syncthreads();

        // ---- projection GEMM (K-split): qkv[64x84] = x[64x224] @ wtile ----
        float pr[4][6];
        if (act) {
            ull acc[4][3] = {};
            const float* wbase = U + gcol * 6;
            const int c0 = kh * 112;
            #pragma unroll 2
            for (int c = c0; c < c0 + 112; ++c) {
                float xa[4];
                *(float4*)xa = *(const float4*)(xT + c * TP + gtok * 4);
                const ull* wp = (const ull*)(wbase + c * 84);
                ull w0 = wp[0], w1 = wp[1], w2 = wp[2];
                #pragma unroll
                for (int u = 0; u < 4; ++u) {
                    ull a = pk2(xa[u], xa[u]);
                    ffma2(acc[u][0], a, w0);
                    ffma2(acc[u][1], a, w1);
                    ffma2(acc[u][2], a, w2);
                }
            }
            #pragma unroll
            for (int u = 0; u < 4; ++u)
                #pragma unroll
                for (int p = 0; p < 3; ++p)
                    upk2(acc[u][p], pr[u][2 * p], pr[u][2 * p + 1]);
            if (kh == 1) {
                #pragma unroll
                for (int p = 0; p < 6; ++p) {
                    float4 v = make_float4(pr[0][p], pr[1][p], pr[2][p], pr[3][p]);
                    *(float4*)(qkvT + (gcol * 6 + p) * QT + gtok * 4) = v;
                }
            }
        }
        __syncthreads();
        if (act && kh == 0) {
            #pragma unroll
            for (int p = 0; p < 6; ++p) {
                float* dst = qkvT + (gcol * 6 + p) * QT + gtok * 4;
                float4 v = *(const float4*)dst;
                v.x += pr[0][p]; v.y += pr[1][p];
                v.z += pr[2][p]; v.w += pr[3][p];
                *(float4*)dst = v;
            }
        }
        __syncthreads();

        // ---- sigma scalars (threads 0..63; coalesced column reads) ----
        if (t < 64) {
            float sq = 0.f, sk = 0.f;
            #pragma unroll
            for (int d = 0; d < 28; ++d) {
                sq = fmaf(qkvT[d * QT + t],        pcq_w[d], sq);
                sk = fmaf(qkvT[(28 + d) * QT + t], pck_w[d], sk);
            }
            Sq[t] = sq + pcq_b[0];
            Sk[t] = sk + pck_b[0];
        }

        // ---- sim = q k^T [64x64]: 256 threads, 4x4 tile, FFMA2 packed ----
        if (t < 256) {
            int ig = t >> 4, jg = t & 15;
            ull acc[4][2] = {};
            #pragma unroll 4
            for (int d = 0; d < 28; ++d) {
                float qa[4];
                *(float4*)qa = *(const float4*)(qkvT + d * QT + ig * 4);
                const ull* kp = (const ull*)(qkvT + (28 + d) * QT + jg * 4);
                ull k0 = kp[0], k1 = kp[1];
                #pragma unroll
                for (int u = 0; u < 4; ++u) {
                    ull a = pk2(qa[u], qa[u]);
                    ffma2(acc[u][0], a, k0);
                    ffma2(acc[u][1], a, k1);
                }
            }
            #pragma unroll
            for (int u = 0; u < 4; ++u) {
                float r[4];
                upk2(acc[u][0], r[0], r[1]);
                upk2(acc[u][1], r[2], r[3]);
                *(float4*)(U + (ig * 4 + u) * SP + jg * 4) =
                    make_float4(r[0], r[1], r[2], r[3]);
            }
        }
        __syncthreads();

        // ---- learned threshold theta (unmodulated sim, diag removed) ----
        if (t < 64) {
            const float* sr = U + t * SP;
            float s = 0.f;
            #pragma unroll 4
            for (int j = 0; j < 64; ++j) s = fmaf(sr[j], mlp1_w[j], s);
            s -= sr[t] * mlp1_w[t];
            t1[t] = s;
        }
        __syncthreads();
        if (t < 64) {
            float s = 0.f;
            #pragma unroll 4
            for (int j = 0; j < 64; ++j) s = fmaf(t1[j], mlp2_w1[j * 64 + t], s);
            s = (s >= 0.f) ? s : 0.1f * s;
            h1[t] = s * mlp2_w2[t];
        }
        __syncthreads();
        if (t == 0) {
            float s = 0.f;
            for (int i = 0; i < 64; ++i) s += h1[i];
            thp[0] = s;
        }
        __syncthreads();

        // ---- sigma modulation + row softmax + threshold gate ----
        if (t < 256) {
            float theta = thp[0];
            int i = t >> 2, p = t & 3;         // 4 lanes per row (warp quad)
            float sqi = Sq[i];
            float* srow = U + i * SP + p * 16;
            float sv[16], mx = -1e30f;
            #pragma unroll
            for (int q4 = 0; q4 < 4; ++q4) {
                float tmp[4];
                *(float4*)tmp = *(const float4*)(srow + q4 * 4);
                #pragma unroll
                for (int jj = 0; jj < 4; ++jj) {
                    float val = tmp[jj] * (sqi * Sk[p * 16 + q4 * 4 + jj]);
                    sv[q4 * 4 + jj] = val;
                    mx = fmaxf(mx, val);
                }
            }
            mx = fmaxf(mx, __shfl_xor_sync(0xffffffffu, mx, 1));
            mx = fmaxf(mx, __shfl_xor_sync(0xffffffffu, mx, 2));
            float ev[16], sum = 0.f;
            #pragma unroll
            for (int jj = 0; jj < 16; ++jj) {
                ev[jj] = __expf(sv[jj] - mx);
                sum += ev[jj];
            }
            sum += __shfl_xor_sync(0xffffffffu, sum, 1);
            sum += __shfl_xor_sync(0xffffffffu, sum, 2);
            float inv = 1.f / sum;
            #pragma unroll
            for (int q4 = 0; q4 < 4; ++q4) {
                float o0 = (sv[q4*4+0] > theta) ? ev[q4*4+0] * inv : 0.f;
                float o1 = (sv[q4*4+1] > theta) ? ev[q4*4+1] * inv : 0.f;
                float o2 = (sv[q4*4+2] > theta) ? ev[q4*4+2] * inv : 0.f;
                float o3 = (sv[q4*4+3] > theta) ? ev[q4*4+3] * inv : 0.f;
                *(float4*)(srow + q4 * 4) = make_float4(o0, o1, o2, o3);
            }
        }
        __syncthreads();

        // ---- o_h = attn @ v (224 threads: 4 tok x 2 d-cols, FFMA2) ----
        if (act1) {
            int dp = gcol * 2;
            ull acc[4] = {};
            const float* v0r = qkvT + (56 + dp) * QT;
            const float* v1r = v0r + QT;
            const float* ar0 = U + gtok * 4 * SP;
            #pragma unroll 2
            for (int j = 0; j < 64; j += 4) {
                float vv0[4], vv1[4];
                *(float4*)vv0 = *(const float4*)(v0r + j);
                *(float4*)vv1 = *(const float4*)(v1r + j);
                float aa[4][4];
                #pragma unroll
                for (int u = 0; u < 4; ++u)
                    *(float4*)aa[u] = *(const float4*)(ar0 + u * SP + j);
                #pragma unroll
                for (int jj = 0; jj < 4; ++jj) {
                    ull vp = pk2(vv0[jj], vv1[jj]);
                    #pragma unroll
                    for (int u = 0; u < 4; ++u)
                        ffma2(acc[u], pk2(aa[u][jj], aa[u][jj]), vp);
                }
            }
            float lo[4], hi[4];
            #pragma unroll
            for (int u = 0; u < 4; ++u) upk2(acc[u], lo[u], hi[u]);
            int ch = h * 28 + dp;
            *(float4*)(oacT + ch * TP + gtok * 4) =
                make_float4(lo[0], lo[1], lo[2], lo[3]);
            *(float4*)(oacT + (ch + 1) * TP + gtok * 4) =
                make_float4(hi[0], hi[1], hi[2], hi[3]);
        }
        __syncthreads();
    } // heads

    // ---- out projection (4 chunks of 56 cols, K-split) + un-roll scatter ----
    for (int e0 = 0; e0 < 224; e0 += 56) {
        for (int idx = t; idx < 224 * 56; idx += 512) {
            int c = idx / 56, j = idx - c * 56;
            U[idx] = w_out[c * 224 + e0 + j];
        }
        __syncthreads();
        float pr[4][4];
        if (act) {
            ull acc[4][2] = {};
            const float* wbase = U + gcol * 4;
            const int c0 = kh * 112;
            #pragma unroll 2
            for (int c = c0; c < c0 + 112; ++c) {
                float xa[4];
                *(float4*)xa = *(const float4*)(oacT + c * TP + gtok * 4);
                const ull* wp = (const ull*)(wbase + c * 56);
                ull w0 = wp[0], w1 = wp[1];
                #pragma unroll
                for (int u = 0; u < 4; ++u) {
                    ull a = pk2(xa[u], xa[u]);
                    ffma2(acc[u][0], a, w0);
                    ffma2(acc[u][1], a, w1);
                }
            }
            #pragma unroll
            for (int u = 0; u < 4; ++u) {
                upk2(acc[u][0], pr[u][0], pr[u][1]);
                upk2(acc[u][1], pr[u][2], pr[u][3]);
            }
            if (kh == 1) {
                #pragma unroll
                for (int u = 0; u < 4; ++u)
                    *(float4*)(Pbuf + (gtok * 4 + u) * 56 + gcol * 4) =
                        make_float4(pr[u][0], pr[u][1], pr[u][2], pr[u][3]);
            }
        }
        __syncthreads();
        if (act && kh == 0) {
            int e = e0 + gcol * 4;
            float b0 = b_out[e], b1 = b_out[e + 1];
            float b2 = b_out[e + 2], b3 = b_out[e + 3];
            #pragma unroll
            for (int u = 0; u < 4; ++u) {
                int tok = gtok * 4 + u;
                float4 pv = *(const float4*)(Pbuf + tok * 56 + gcol * 4);
                int r  = wh * 8 + (tok >> 3), c = ww * 8 + (tok & 7);
                int fr = (r + 252) & 255, fc = (c + 252) & 255;  // un-shift
                float* op = out +
                    (((size_t)(bi * 256 + fr)) * 256 + fc) * 224 + e;
                *(float4*)op = make_float4(pr[u][0] + pv.x + b0,
                                           pr[u][1] + pv.y + b1,
                                           pr[u][2] + pv.z + b2,
                                           pr[u][3] + pv.w + b3);
            }
        }
        __syncthreads();
    }
}

// floats: 2*224*68 + 84*68 + 224*84 + 4*64 + 1 = 55249
#define FA_SMEM_BYTES (55249 * 4)

extern "C" void kernel_launch(void* const* d_in, const int* in_sizes, int n_in,
                              void* d_out, int out_size) {
    (void)in_sizes; (void)n_in; (void)out_size;
    const float* x       = (const float*)d_in[0];
    const float* w_qk    = (const float*)d_in[1];
    const float* w_v     = (const float*)d_in[2];
    const float* w_out   = (const float*)d_in[3];
    const float* b_out   = (const float*)d_in[4];
    const float* pcq_w   = (const float*)d_in[5];
    const float* pcq_b   = (const float*)d_in[6];
    const float* pck_w   = (const float*)d_in[7];
    const float* pck_b   = (const float*)d_in[8];
    const float* mlp1_w  = (const float*)d_in[9];
    const float* mlp2_w1 = (const float*)d_in[10];
    const float* mlp2_w2 = (const float*)d_in[11];
    float* out = (float*)d_out;

    cudaFuncSetAttribute(fa_window_kernel,
                         cudaFuncAttributeMaxDynamicSharedMemorySize,
                         FA_SMEM_BYTES);
    fa_window_kernel<<<4096, 512, FA_SMEM_BYTES>>>(
        x, w_qk, w_v, w_out, b_out, pcq_w, pcq_b, pck_w, pck_b,
        mlp1_w, mlp2_w1, mlp2_w2, out);
}

// round 5
// speedup vs baseline: 1.5796x; 1.1530x over previous
#include <cuda_runtime.h>
#include <math.h>

// ---------------------------------------------------------------------------
// Shifted-window attention, fused: one CTA (256 thr) per 8x8 window,
// 2 CTAs/SM (smem 110.7KB). Per-head pipeline with per-head out-projection
// into persistent register accumulators. FFMA2 (packed f32x2) everywhere.
// ---------------------------------------------------------------------------

typedef unsigned long long ull;

__device__ __forceinline__ ull pk2(float lo, float hi) {
    ull r; asm("mov.b64 %0, {%1, %2};" : "=l"(r) : "f"(lo), "f"(hi)); return r;
}
__device__ __forceinline__ void upk2(ull v, float& lo, float& hi) {
    asm("mov.b64 {%0, %1}, %2;" : "=f"(lo), "=f"(hi) : "l"(v));
}
__device__ __forceinline__ void ffma2(ull& d, ull a, ull b) {
    asm("fma.rn.f32x2 %0, %1, %2, %0;" : "+l"(d) : "l"(a), "l"(b));
}

#define XP  64   // xT pitch (column-swizzled)
#define QKP 68   // qkT pitch
#define VP  30   // vT pitch (token-major v)
#define SP  68   // sim pitch
#define OP  64   // Ohead pitch

// smem floats: xT 14336 + qkT 3808 + vT 1920 + U 6300 + Oh 1792 + 194 = 28350
#define FA_SMEM_BYTES (28350 * 4)

__global__ void __launch_bounds__(256, 2)
fa_window_kernel(const float* __restrict__ x,
                 const float* __restrict__ w_qk,
                 const float* __restrict__ w_v,
                 const float* __restrict__ w_out,
                 const float* __restrict__ b_out,
                 const float* __restrict__ pcq_w,
                 const float* __restrict__ pcq_b,
                 const float* __restrict__ pck_w,
                 const float* __restrict__ pck_b,
                 const float* __restrict__ mlp1_w,
                 const float* __restrict__ mlp2_w1,
                 const float* __restrict__ mlp2_w2,
                 float* __restrict__ out)
{
    extern __shared__ float sm[];
    float* xT  = sm;                 // [224][64] swizzled columns
    float* qkT = xT  + 224 * XP;     // [56][68]  q rows 0..27, k rows 28..55
    float* vT  = qkT + 56 * QKP;     // [64][30]  v token-major
    float* U   = vT  + 64 * VP;      // 6300: wtile chunk [75][84] / sim [64][68] / wout [28][224]
    float* Oh  = U   + 6300;         // [28][64]  per-head o (channel-major)
    float* Sq  = Oh  + 28 * OP;      // [64]
    float* Sk  = Sq  + 64;           // [64]
    float* t1s = Sk  + 64;           // [64]
    float* part= t1s + 64;           // [2] theta partials

    const int t  = threadIdx.x;
    const int w  = blockIdx.x;
    const int bi = w >> 10;
    const int wh = (w >> 5) & 31;
    const int ww = w & 31;

    // ---- gather rolled window: rolled[r][c] = x[(r-4)%256][(c-4)%256] ----
    for (int idx = t; idx < 64 * 224; idx += 256) {
        int tok = idx / 224, ch = idx - tok * 224;
        int r  = wh * 8 + (tok >> 3), c = ww * 8 + (tok & 7);
        int sr = (r + 252) & 255, sc = (c + 252) & 255;
        xT[ch * XP + ((tok + (ch & 60)) & 63)] =
            x[(((size_t)(bi * 256 + sr)) * 256 + sc) * 224 + ch];
    }
    __syncthreads();

    // projection tiling: 224 active threads (gcol 0..13 inner, gtok 0..15)
    const int pcol = t % 14;
    const int ptok = (t / 14) & 15;
    const bool pact = (t < 224);

    // out-proj tiling: 256 threads (gch 0..15 inner x gtok 0..15), 4tok x 14ch
    const int gch = t & 15;
    const int gtk = t >> 4;

    ull oacc[4][7];                  // persistent out accumulator (56 floats)
    #pragma unroll
    for (int u = 0; u < 4; ++u)
        #pragma unroll
        for (int k = 0; k < 7; ++k) oacc[u][k] = 0ull;

    for (int h = 0; h < 8; ++h) {
        // ================= projection (full-K, 3 staged chunks) =========
        ull pacc[4][3];
        #pragma unroll
        for (int u = 0; u < 4; ++u)
            #pragma unroll
            for (int p = 0; p < 3; ++p) pacc[u][p] = 0ull;

        for (int ck = 0; ck < 3; ++ck) {
            const int c0 = ck * 75;
            const int L  = (ck == 2) ? 74 : 75;
            for (int idx = t; idx < L * 84; idx += 256) {
                int c = idx / 84, j = idx - c * 84;
                int col = c0 + c;
                float wv;
                if (j < 28)      wv = w_qk[col * 448 + h * 28 + j];
                else if (j < 56) wv = w_qk[col * 448 + 224 + h * 28 + (j - 28)];
                else             wv = w_v [col * 224 + h * 28 + (j - 56)];
                U[idx] = wv;
            }
            __syncthreads();
            if (pact) {
                const float* wb = U + pcol * 6;
                #pragma unroll 2
                for (int c = 0; c < L; ++c) {
                    int cc = c0 + c;
                    float xa[4];
                    *(float4*)xa = *(const float4*)
                        (xT + cc * XP + ((ptok * 4 + (cc & 60)) & 63));
                    const ull* wp = (const ull*)(wb + c * 84);
                    ull w0 = wp[0], w1 = wp[1], w2 = wp[2];
                    #pragma unroll
                    for (int u = 0; u < 4; ++u) {
                        ull a = pk2(xa[u], xa[u]);
                        ffma2(pacc[u][0], a, w0);
                        ffma2(pacc[u][1], a, w1);
                        ffma2(pacc[u][2], a, w2);
                    }
                }
            }
            __syncthreads();
        }
        // write q/k (channel-major) and v (token-major)
        if (pact) {
            #pragma unroll
            for (int p = 0; p < 3; ++p) {
                float lo[4], hi[4];
                #pragma unroll
                for (int u = 0; u < 4; ++u) upk2(pacc[u][p], lo[u], hi[u]);
                int r0 = pcol * 6 + 2 * p;
                if (r0 < 56) {
                    *(float4*)(qkT + r0 * QKP + ptok * 4) =
                        make_float4(lo[0], lo[1], lo[2], lo[3]);
                } else {
                    #pragma unroll
                    for (int u = 0; u < 4; ++u)
                        vT[(ptok * 4 + u) * VP + (r0 - 56)] = lo[u];
                }
                int r1 = r0 + 1;
                if (r1 < 56) {
                    *(float4*)(qkT + r1 * QKP + ptok * 4) =
                        make_float4(hi[0], hi[1], hi[2], hi[3]);
                } else {
                    #pragma unroll
                    for (int u = 0; u < 4; ++u)
                        vT[(ptok * 4 + u) * VP + (r1 - 56)] = hi[u];
                }
            }
        }
        __syncthreads();

        // ================= sim = q k^T  (256 thr) + sigma (t<64) =========
        {
            int ig = t >> 4, jg = t & 15;
            ull sacc[4][2];
            #pragma unroll
            for (int u = 0; u < 4; ++u) { sacc[u][0] = 0ull; sacc[u][1] = 0ull; }
            #pragma unroll 4
            for (int d = 0; d < 28; ++d) {
                float qa[4];
                *(float4*)qa = *(const float4*)(qkT + d * QKP + ig * 4);
                const ull* kp = (const ull*)(qkT + (28 + d) * QKP + jg * 4);
                ull k0 = kp[0], k1 = kp[1];
                #pragma unroll
                for (int u = 0; u < 4; ++u) {
                    ull a = pk2(qa[u], qa[u]);
                    ffma2(sacc[u][0], a, k0);
                    ffma2(sacc[u][1], a, k1);
                }
            }
            #pragma unroll
            for (int u = 0; u < 4; ++u) {
                float r0, r1, r2, r3;
                upk2(sacc[u][0], r0, r1);
                upk2(sacc[u][1], r2, r3);
                *(float4*)(U + (ig * 4 + u) * SP + jg * 4) =
                    make_float4(r0, r1, r2, r3);
            }
        }
        if (t < 64) {
            float sq = 0.f, sk = 0.f;
            #pragma unroll
            for (int d = 0; d < 28; ++d) {
                sq = fmaf(qkT[d * QKP + t],        __ldg(pcq_w + d), sq);
                sk = fmaf(qkT[(28 + d) * QKP + t], __ldg(pck_w + d), sk);
            }
            Sq[t] = sq + __ldg(pcq_b);
            Sk[t] = sk + __ldg(pck_b);
        }
        __syncthreads();

        // ================= theta (unmodulated sim, diag removed) =========
        if (t < 64) {
            const float* sr = U + t * SP;
            float s = 0.f;
            #pragma unroll
            for (int q4 = 0; q4 < 16; ++q4) {
                float4 sv4 = *(const float4*)(sr + q4 * 4);
                float4 m4  = __ldg((const float4*)(mlp1_w + q4 * 4));
                s = fmaf(sv4.x, m4.x, s); s = fmaf(sv4.y, m4.y, s);
                s = fmaf(sv4.z, m4.z, s); s = fmaf(sv4.w, m4.w, s);
            }
            s -= sr[t] * __ldg(mlp1_w + t);
            t1s[t] = s;
        }
        __syncthreads();
        if (t < 64) {
            float s = 0.f;
            #pragma unroll 4
            for (int j = 0; j < 64; ++j)
                s = fmaf(t1s[j], __ldg(mlp2_w1 + j * 64 + t), s);
            s = (s >= 0.f) ? s : 0.1f * s;       // LeakyReLU(0.1)
            s *= __ldg(mlp2_w2 + t);
            #pragma unroll
            for (int o = 16; o > 0; o >>= 1)
                s += __shfl_xor_sync(0xffffffffu, s, o);
            if ((t & 31) == 0) part[t >> 5] = s;
        }
        __syncthreads();

        // ======= sigma modulation + row softmax + threshold gate =========
        {
            float theta = part[0] + part[1];
            int i = t >> 2, p = t & 3;           // 4 lanes per row (warp quad)
            float sqi = Sq[i];
            float* srow = U + i * SP + p * 16;
            float sv[16], mx = -1e30f;
            #pragma unroll
            for (int q4 = 0; q4 < 4; ++q4) {
                float tmp[4];
                *(float4*)tmp = *(const float4*)(srow + q4 * 4);
                #pragma unroll
                for (int jj = 0; jj < 4; ++jj) {
                    float val = tmp[jj] * (sqi * Sk[p * 16 + q4 * 4 + jj]);
                    sv[q4 * 4 + jj] = val;
                    mx = fmaxf(mx, val);
                }
            }
            mx = fmaxf(mx, __shfl_xor_sync(0xffffffffu, mx, 1));
            mx = fmaxf(mx, __shfl_xor_sync(0xffffffffu, mx, 2));
            float ev[16], sum = 0.f;
            #pragma unroll
            for (int jj = 0; jj < 16; ++jj) {
                ev[jj] = __expf(sv[jj] - mx);
                sum += ev[jj];
            }
            sum += __shfl_xor_sync(0xffffffffu, sum, 1);
            sum += __shfl_xor_sync(0xffffffffu, sum, 2);
            float inv = 1.f / sum;
            #pragma unroll
            for (int q4 = 0; q4 < 4; ++q4) {
                float o0 = (sv[q4*4+0] > theta) ? ev[q4*4+0] * inv : 0.f;
                float o1 = (sv[q4*4+1] > theta) ? ev[q4*4+1] * inv : 0.f;
                float o2 = (sv[q4*4+2] > theta) ? ev[q4*4+2] * inv : 0.f;
                float o3 = (sv[q4*4+3] > theta) ? ev[q4*4+3] * inv : 0.f;
                *(float4*)(srow + q4 * 4) = make_float4(o0, o1, o2, o3);
            }
        }
        __syncthreads();

        // ================= o_h = attn @ v  -> Oh [28][64] ================
        {
            int atok = t & 15;                   // token-group (broadcast a)
            int adc  = t >> 4;                   // d-pair 0..13 (valid < 14)
            if (adc < 14) {
                ull acc4[4];
                #pragma unroll
                for (int u = 0; u < 4; ++u) acc4[u] = 0ull;
                const float* ar = U + atok * 4 * SP;
                const float* vr = vT + adc * 2;
                #pragma unroll 2
                for (int j = 0; j < 64; j += 4) {
                    float aa[4][4];
                    #pragma unroll
                    for (int u = 0; u < 4; ++u)
                        *(float4*)aa[u] = *(const float4*)(ar + u * SP + j);
                    ull v0 = *(const ull*)(vr + (j + 0) * VP);
                    ull v1 = *(const ull*)(vr + (j + 1) * VP);
                    ull v2 = *(const ull*)(vr + (j + 2) * VP);
                    ull v3 = *(const ull*)(vr + (j + 3) * VP);
                    #pragma unroll
                    for (int u = 0; u < 4; ++u) {
                        ffma2(acc4[u], pk2(aa[u][0], aa[u][0]), v0);
                        ffma2(acc4[u], pk2(aa[u][1], aa[u][1]), v1);
                        ffma2(acc4[u], pk2(aa[u][2], aa[u][2]), v2);
                        ffma2(acc4[u], pk2(aa[u][3], aa[u][3]), v3);
                    }
                }
                float lo[4], hi[4];
                #pragma unroll
                for (int u = 0; u < 4; ++u) upk2(acc4[u], lo[u], hi[u]);
                *(float4*)(Oh + (2 * adc) * OP + atok * 4) =
                    make_float4(lo[0], lo[1], lo[2], lo[3]);
                *(float4*)(Oh + (2 * adc + 1) * OP + atok * 4) =
                    make_float4(hi[0], hi[1], hi[2], hi[3]);
            }
        }
        __syncthreads();

        // ====== per-head out-projection: oacc += o_h @ w_out[h*28:, :] ===
        for (int idx = t; idx < 28 * 224; idx += 256) {
            int row = idx / 224, col = idx - row * 224;
            U[idx] = w_out[(h * 28 + row) * 224 + col];
        }
        __syncthreads();
        {
            const float* wb = U + gch * 14;
            #pragma unroll 2
            for (int d = 0; d < 28; ++d) {
                float xa[4];
                *(float4*)xa = *(const float4*)(Oh + d * OP + gtk * 4);
                const ull* wp = (const ull*)(wb + d * 224);
                ull wv[7];
                #pragma unroll
                for (int k = 0; k < 7; ++k) wv[k] = wp[k];
                #pragma unroll
                for (int u = 0; u < 4; ++u) {
                    ull a = pk2(xa[u], xa[u]);
                    #pragma unroll
                    for (int k = 0; k < 7; ++k) ffma2(oacc[u][k], a, wv[k]);
                }
            }
        }
        __syncthreads();   // U reused by next head's weight staging
    } // heads

    // ---- bias add + un-shift scatter ----
    {
        const int e = gch * 14;
        float bv[14];
        #pragma unroll
        for (int k = 0; k < 14; ++k) bv[k] = __ldg(b_out + e + k);
        #pragma unroll
        for (int u = 0; u < 4; ++u) {
            int tok = gtk * 4 + u;
            int r  = wh * 8 + (tok >> 3), c = ww * 8 + (tok & 7);
            int fr = (r + 252) & 255, fc = (c + 252) & 255;
            float* op = out + (((size_t)(bi * 256 + fr)) * 256 + fc) * 224 + e;
            #pragma unroll
            for (int k = 0; k < 7; ++k) {
                float lo, hi;
                upk2(oacc[u][k], lo, hi);
                float2 st = make_float2(lo + bv[2 * k], hi + bv[2 * k + 1]);
                *(float2*)(op + 2 * k) = st;
            }
        }
    }
}

extern "C" void kernel_launch(void* const* d_in, const int* in_sizes, int n_in,
                              void* d_out, int out_size) {
    (void)in_sizes; (void)n_in; (void)out_size;
    const float* x       = (const float*)d_in[0];
    const float* w_qk    = (const float*)d_in[1];
    const float* w_v     = (const float*)d_in[2];
    const float* w_out   = (const float*)d_in[3];
    const float* b_out   = (const float*)d_in[4];
    const float* pcq_w   = (const float*)d_in[5];
    const float* pcq_b   = (const float*)d_in[6];
    const float* pck_w   = (const float*)d_in[7];
    const float* pck_b   = (const float*)d_in[8];
    const float* mlp1_w  = (const float*)d_in[9];
    const float* mlp2_w1 = (const float*)d_in[10];
    const float* mlp2_w2 = (const float*)d_in[11];
    float* out = (float*)d_out;

    cudaFuncSetAttribute(fa_window_kernel,
                         cudaFuncAttributeMaxDynamicSharedMemorySize,
                         FA_SMEM_BYTES);
    fa_window_kernel<<<4096, 256, FA_SMEM_BYTES>>>(
        x, w_qk, w_v, w_out, b_out, pcq_w, pcq_b, pck_w, pck_b,
        mlp1_w, mlp2_w1, mlp2_w2, out);
}

// round 6
// speedup vs baseline: 1.7454x; 1.1049x over previous
#include <cuda_runtime.h>
#include <math.h>

// ---------------------------------------------------------------------------
// Shifted-window attention, fused: one CTA (256 thr) per 8x8 window, 2 CTAs/SM.
// Weights repacked per-head in GMEM (prep kernel) and read warp-uniform via
// LDG (no smem staging). All GEMMs: warp->cols, lane->token-pairs, FFMA2.
// ---------------------------------------------------------------------------

typedef unsigned long long ull;

__device__ float g_wqkv[8 * 224 * 84];   // [h][c][j] j: q0..27 k28..55 v56..83

__device__ __forceinline__ ull pk2(float lo, float hi) {
    ull r; asm("mov.b64 %0, {%1, %2};" : "=l"(r) : "f"(lo), "f"(hi)); return r;
}
__device__ __forceinline__ void upk2(ull v, float& lo, float& hi) {
    asm("mov.b64 {%0, %1}, %2;" : "=f"(lo), "=f"(hi) : "l"(v));
}
__device__ __forceinline__ void ffma2(ull& d, ull a, ull b) {
    asm("fma.rn.f32x2 %0, %1, %2, %0;" : "+l"(d) : "l"(a), "l"(b));
}

#define XP  64
#define QKP 68
#define VP  30
#define SP  68
#define OP  64

// smem floats: 14336 + 3808 + 1920 + 4352 + 1792 + 200 = 26408
#define FA_SMEM_BYTES (26408 * 4)

__global__ void repack_wqkv(const float* __restrict__ w_qk,
                            const float* __restrict__ w_v) {
    int idx = blockIdx.x * 256 + threadIdx.x;
    if (idx >= 8 * 224 * 84) return;
    int j = idx % 84;
    int c = (idx / 84) % 224;
    int h = idx / (84 * 224);
    float v;
    if (j < 28)      v = w_qk[c * 448 + h * 28 + j];
    else if (j < 56) v = w_qk[c * 448 + 224 + h * 28 + (j - 28)];
    else             v = w_v [c * 224 + h * 28 + (j - 56)];
    g_wqkv[idx] = v;
}

__global__ void __launch_bounds__(256, 2)
fa_window_kernel(const float* __restrict__ x,
                 const float* __restrict__ w_out,
                 const float* __restrict__ b_out,
                 const float* __restrict__ pcq_w,
                 const float* __restrict__ pcq_b,
                 const float* __restrict__ pck_w,
                 const float* __restrict__ pck_b,
                 const float* __restrict__ mlp1_w,
                 const float* __restrict__ mlp2_w1,
                 const float* __restrict__ mlp2_w2,
                 float* __restrict__ out)
{
    extern __shared__ float sm[];
    float* xT   = sm;                    // [224][64] swizzled tokens
    float* qkT  = xT   + 224 * XP;       // [56][68]  q rows 0..27, k rows 28..55
    float* vT   = qkT  + 56 * QKP;       // [64][30]  v token-major
    float* simb = vT   + 64 * VP;        // [64][68]
    float* Oh   = simb + 64 * SP;        // [28][64]  per-head o (channel-major)
    float* Sq   = Oh   + 28 * OP;        // [64]
    float* Sk   = Sq   + 64;             // [64]
    float* t1s  = Sk   + 64;             // [64]
    float* part = t1s  + 64;             // [8]

    const int t  = threadIdx.x;
    const int wp = t >> 5;
    const int ln = t & 31;
    const int l2 = ln * 2;
    const int w  = blockIdx.x;
    const int bi = w >> 10;
    const int wh = (w >> 5) & 31;
    const int ww = w & 31;

    // ---- gather rolled window: rolled[r][c] = x[(r-4)%256][(c-4)%256] ----
    for (int idx = t; idx < 64 * 224; idx += 256) {
        int tok = idx / 224, ch = idx - tok * 224;
        int r  = wh * 8 + (tok >> 3), c = ww * 8 + (tok & 7);
        int sr = (r + 252) & 255, sc = (c + 252) & 255;
        xT[ch * XP + ((tok + (ch & 60)) & 63)] =
            x[(((size_t)(bi * 256 + sr)) * 256 + sc) * 224 + ch];
    }
    __syncthreads();

    ull oa[2][14];                        // persistent out accumulator
    #pragma unroll
    for (int u = 0; u < 2; ++u)
        #pragma unroll
        for (int k = 0; k < 14; ++k) oa[u][k] = 0ull;

    for (int h = 0; h < 8; ++h) {
        // ============ projection: 7 warps x 12 cols, lane -> 2 tokens ====
        if (wp < 7) {
            ull pa[2][6];
            #pragma unroll
            for (int u = 0; u < 2; ++u)
                #pragma unroll
                for (int p = 0; p < 6; ++p) pa[u][p] = 0ull;
            const float* wg = g_wqkv + h * (224 * 84) + wp * 12;
            for (int c4 = 0; c4 < 224; c4 += 4) {
                int sw = (l2 + (c4 & 60)) & 63;
                #pragma unroll
                for (int cc = 0; cc < 4; ++cc) {
                    int c = c4 + cc;
                    float2 xv = *(const float2*)(xT + c * XP + sw);
                    const ulonglong2* wr = (const ulonglong2*)(wg + c * 84);
                    ulonglong2 wA = wr[0], wB = wr[1], wC = wr[2];
                    ull a0 = pk2(xv.x, xv.x), a1 = pk2(xv.y, xv.y);
                    ffma2(pa[0][0], a0, wA.x); ffma2(pa[0][1], a0, wA.y);
                    ffma2(pa[0][2], a0, wB.x); ffma2(pa[0][3], a0, wB.y);
                    ffma2(pa[0][4], a0, wC.x); ffma2(pa[0][5], a0, wC.y);
                    ffma2(pa[1][0], a1, wA.x); ffma2(pa[1][1], a1, wA.y);
                    ffma2(pa[1][2], a1, wB.x); ffma2(pa[1][3], a1, wB.y);
                    ffma2(pa[1][4], a1, wC.x); ffma2(pa[1][5], a1, wC.y);
                }
            }
            // store 6 col-pairs -> qkT (channel-major) or vT (token-major)
            #pragma unroll
            for (int p = 0; p < 6; ++p) {
                int c0 = wp * 12 + 2 * p;
                float l0, h0, l1, h1;
                upk2(pa[0][p], l0, h0);    // token l2:   cols c0, c0+1
                upk2(pa[1][p], l1, h1);    // token l2+1: cols c0, c0+1
                if (c0 < 56) {
                    *(float2*)(qkT + c0 * QKP + l2)       = make_float2(l0, l1);
                    *(float2*)(qkT + (c0 + 1) * QKP + l2) = make_float2(h0, h1);
                } else {
                    *(float2*)(vT + l2 * VP + (c0 - 56))       = make_float2(l0, h0);
                    *(float2*)(vT + (l2 + 1) * VP + (c0 - 56)) = make_float2(l1, h1);
                }
            }
        }
        __syncthreads();

        // ============ sim = q k^T : warp -> 8 k-tokens, lane -> 2 q-rows ==
        {
            ull sa[2][4];
            #pragma unroll
            for (int u = 0; u < 2; ++u)
                #pragma unroll
                for (int p = 0; p < 4; ++p) sa[u][p] = 0ull;
            const float* kb = qkT + 28 * QKP + wp * 8;
            #pragma unroll 4
            for (int d = 0; d < 28; ++d) {
                float q0 = qkT[d * QKP + ln];
                float q1 = qkT[d * QKP + ln + 32];
                const ulonglong2* kr = (const ulonglong2*)(kb + d * QKP);
                ulonglong2 kA = kr[0], kB = kr[1];
                ull a0 = pk2(q0, q0), a1 = pk2(q1, q1);
                ffma2(sa[0][0], a0, kA.x); ffma2(sa[0][1], a0, kA.y);
                ffma2(sa[0][2], a0, kB.x); ffma2(sa[0][3], a0, kB.y);
                ffma2(sa[1][0], a1, kA.x); ffma2(sa[1][1], a1, kA.y);
                ffma2(sa[1][2], a1, kB.x); ffma2(sa[1][3], a1, kB.y);
            }
            #pragma unroll
            for (int u = 0; u < 2; ++u) {
                float r0,r1,r2,r3,r4,r5,r6,r7;
                upk2(sa[u][0], r0, r1); upk2(sa[u][1], r2, r3);
                upk2(sa[u][2], r4, r5); upk2(sa[u][3], r6, r7);
                float* dst = simb + (ln + u * 32) * SP + wp * 8;
                *(float4*)dst       = make_float4(r0, r1, r2, r3);
                *(float4*)(dst + 4) = make_float4(r4, r5, r6, r7);
            }
        }
        // ---- sigma scalars on 128 threads (after sim FMA, same phase) ----
        if (t < 128) {
            int tok = t & 63;
            int isK = t >> 6;
            const float* qb = qkT + isK * 28 * QKP + tok;
            const float* pw = isK ? pck_w : pcq_w;
            float s = 0.f;
            #pragma unroll
            for (int d = 0; d < 28; ++d)
                s = fmaf(qb[d * QKP], __ldg(pw + d), s);
            s += __ldg(isK ? pck_b : pcq_b);
            (isK ? Sk : Sq)[tok] = s;
        }
        __syncthreads();

        // ============ theta: t1 = sim_nd @ mlp1_w (quad-split) ============
        {
            int row = t >> 2, p = t & 3;
            const float* sr = simb + row * SP + p * 16;
            float s = 0.f;
            #pragma unroll
            for (int q4 = 0; q4 < 4; ++q4) {
                float4 sv = *(const float4*)(sr + q4 * 4);
                float4 m  = __ldg((const float4*)(mlp1_w + p * 16 + q4 * 4));
                s = fmaf(sv.x, m.x, s); s = fmaf(sv.y, m.y, s);
                s = fmaf(sv.z, m.z, s); s = fmaf(sv.w, m.w, s);
            }
            if (p == (row >> 4))
                s -= simb[row * SP + row] * __ldg(mlp1_w + row);
            s += __shfl_xor_sync(0xffffffffu, s, 1);
            s += __shfl_xor_sync(0xffffffffu, s, 2);
            if (p == 0) t1s[row] = s;
        }
        __syncthreads();
        // ============ h1 + theta reduce ===================================
        {
            int i = t >> 2, p = t & 3;
            float s = 0.f;
            #pragma unroll 4
            for (int jj = 0; jj < 16; ++jj) {
                int j = p * 16 + jj;
                s = fmaf(t1s[j], __ldg(mlp2_w1 + j * 64 + i), s);
            }
            s += __shfl_xor_sync(0xffffffffu, s, 1);
            s += __shfl_xor_sync(0xffffffffu, s, 2);
            if (p == 0) {
                s = (s >= 0.f) ? s : 0.1f * s;   // LeakyReLU(0.1)
                s *= __ldg(mlp2_w2 + i);
            } else s = 0.f;
            s += __shfl_xor_sync(0xffffffffu, s, 4);
            s += __shfl_xor_sync(0xffffffffu, s, 8);
            s += __shfl_xor_sync(0xffffffffu, s, 16);
            if (ln == 0) part[wp] = s;
        }
        __syncthreads();

        // ======= sigma modulation + row softmax + threshold gate =========
        {
            float theta = ((part[0] + part[1]) + (part[2] + part[3]))
                        + ((part[4] + part[5]) + (part[6] + part[7]));
            int i = t >> 2, p = t & 3;
            float sqi = Sq[i];
            float* srow = simb + i * SP + p * 16;
            float sv[16], mx = -1e30f;
            #pragma unroll
            for (int q4 = 0; q4 < 4; ++q4) {
                float tmp[4];
                *(float4*)tmp = *(const float4*)(srow + q4 * 4);
                #pragma unroll
                for (int jj = 0; jj < 4; ++jj) {
                    float val = tmp[jj] * (sqi * Sk[p * 16 + q4 * 4 + jj]);
                    sv[q4 * 4 + jj] = val;
                    mx = fmaxf(mx, val);
                }
            }
            mx = fmaxf(mx, __shfl_xor_sync(0xffffffffu, mx, 1));
            mx = fmaxf(mx, __shfl_xor_sync(0xffffffffu, mx, 2));
            float ev[16], sum = 0.f;
            #pragma unroll
            for (int jj = 0; jj < 16; ++jj) {
                ev[jj] = __expf(sv[jj] - mx);
                sum += ev[jj];
            }
            sum += __shfl_xor_sync(0xffffffffu, sum, 1);
            sum += __shfl_xor_sync(0xffffffffu, sum, 2);
            float inv = 1.f / sum;
            #pragma unroll
            for (int q4 = 0; q4 < 4; ++q4) {
                float o0 = (sv[q4*4+0] > theta) ? ev[q4*4+0] * inv : 0.f;
                float o1 = (sv[q4*4+1] > theta) ? ev[q4*4+1] * inv : 0.f;
                float o2 = (sv[q4*4+2] > theta) ? ev[q4*4+2] * inv : 0.f;
                float o3 = (sv[q4*4+3] > theta) ? ev[q4*4+3] * inv : 0.f;
                *(float4*)(srow + q4 * 4) = make_float4(o0, o1, o2, o3);
            }
        }
        __syncthreads();

        // ============ o_h = attn @ v -> Oh [28][64] =======================
        {
            int atok = t & 15, adc = t >> 4;
            if (adc < 14) {
                ull acc4[4];
                #pragma unroll
                for (int u = 0; u < 4; ++u) acc4[u] = 0ull;
                const float* ar = simb + atok * 4 * SP;
                const float* vr = vT + adc * 2;
                #pragma unroll 2
                for (int j = 0; j < 64; j += 4) {
                    float aa[4][4];
                    #pragma unroll
                    for (int u = 0; u < 4; ++u)
                        *(float4*)aa[u] = *(const float4*)(ar + u * SP + j);
                    ull v0 = *(const ull*)(vr + (j + 0) * VP);
                    ull v1 = *(const ull*)(vr + (j + 1) * VP);
                    ull v2 = *(const ull*)(vr + (j + 2) * VP);
                    ull v3 = *(const ull*)(vr + (j + 3) * VP);
                    #pragma unroll
                    for (int u = 0; u < 4; ++u) {
                        ffma2(acc4[u], pk2(aa[u][0], aa[u][0]), v0);
                        ffma2(acc4[u], pk2(aa[u][1], aa[u][1]), v1);
                        ffma2(acc4[u], pk2(aa[u][2], aa[u][2]), v2);
                        ffma2(acc4[u], pk2(aa[u][3], aa[u][3]), v3);
                    }
                }
                float lo[4], hi[4];
                #pragma unroll
                for (int u = 0; u < 4; ++u) upk2(acc4[u], lo[u], hi[u]);
                *(float4*)(Oh + (2 * adc) * OP + atok * 4) =
                    make_float4(lo[0], lo[1], lo[2], lo[3]);
                *(float4*)(Oh + (2 * adc + 1) * OP + atok * 4) =
                    make_float4(hi[0], hi[1], hi[2], hi[3]);
            }
        }
        __syncthreads();

        // ===== out-projection: warp -> 28 cols (16+12 split), uniform LDG =
        {
            const float* wg = w_out + (size_t)(h * 28) * 224 + wp * 28;
            #pragma unroll 2
            for (int d = 0; d < 28; ++d) {
                float2 ov = *(const float2*)(Oh + d * OP + l2);
                ull a0 = pk2(ov.x, ov.x), a1 = pk2(ov.y, ov.y);
                const ulonglong2* wr = (const ulonglong2*)(wg + d * 224);
                {   // cols 0..15
                    ulonglong2 wA = wr[0], wB = wr[1];
                    ulonglong2 wC = wr[2], wD = wr[3];
                    ffma2(oa[0][0], a0, wA.x); ffma2(oa[0][1], a0, wA.y);
                    ffma2(oa[0][2], a0, wB.x); ffma2(oa[0][3], a0, wB.y);
                    ffma2(oa[0][4], a0, wC.x); ffma2(oa[0][5], a0, wC.y);
                    ffma2(oa[0][6], a0, wD.x); ffma2(oa[0][7], a0, wD.y);
                    ffma2(oa[1][0], a1, wA.x); ffma2(oa[1][1], a1, wA.y);
                    ffma2(oa[1][2], a1, wB.x); ffma2(oa[1][3], a1, wB.y);
                    ffma2(oa[1][4], a1, wC.x); ffma2(oa[1][5], a1, wC.y);
                    ffma2(oa[1][6], a1, wD.x); ffma2(oa[1][7], a1, wD.y);
                }
                {   // cols 16..27
                    ulonglong2 wE = wr[4], wF = wr[5], wG = wr[6];
                    ffma2(oa[0][8],  a0, wE.x); ffma2(oa[0][9],  a0, wE.y);
                    ffma2(oa[0][10], a0, wF.x); ffma2(oa[0][11], a0, wF.y);
                    ffma2(oa[0][12], a0, wG.x); ffma2(oa[0][13], a0, wG.y);
                    ffma2(oa[1][8],  a1, wE.x); ffma2(oa[1][9],  a1, wE.y);
                    ffma2(oa[1][10], a1, wF.x); ffma2(oa[1][11], a1, wF.y);
                    ffma2(oa[1][12], a1, wG.x); ffma2(oa[1][13], a1, wG.y);
                }
            }
        }
        __syncthreads();   // Oh / qkT / vT / simb reused next head
    } // heads

    // ---- bias add + un-shift scatter: lane -> 2 tokens, warp -> 28 cols --
    {
        const float* bb = b_out + wp * 28;
        #pragma unroll
        for (int u = 0; u < 2; ++u) {
            int tok = l2 + u;
            int r  = wh * 8 + (tok >> 3), c = ww * 8 + (tok & 7);
            int fr = (r + 252) & 255, fc = (c + 252) & 255;
            float* op = out +
                (((size_t)(bi * 256 + fr)) * 256 + fc) * 224 + wp * 28;
            #pragma unroll
            for (int k = 0; k < 7; ++k) {
                float a, b, c2, d2;
                upk2(oa[u][2 * k],     a,  b);
                upk2(oa[u][2 * k + 1], c2, d2);
                float4 bv = __ldg((const float4*)(bb + 4 * k));
                *(float4*)(op + 4 * k) =
                    make_float4(a + bv.x, b + bv.y, c2 + bv.z, d2 + bv.w);
            }
        }
    }
}

extern "C" void kernel_launch(void* const* d_in, const int* in_sizes, int n_in,
                              void* d_out, int out_size) {
    (void)in_sizes; (void)n_in; (void)out_size;
    const float* x       = (const float*)d_in[0];
    const float* w_qk    = (const float*)d_in[1];
    const float* w_v     = (const float*)d_in[2];
    const float* w_out   = (const float*)d_in[3];
    const float* b_out   = (const float*)d_in[4];
    const float* pcq_w   = (const float*)d_in[5];
    const float* pcq_b   = (const float*)d_in[6];
    const float* pck_w   = (const float*)d_in[7];
    const float* pck_b   = (const float*)d_in[8];
    const float* mlp1_w  = (const float*)d_in[9];
    const float* mlp2_w1 = (const float*)d_in[10];
    const float* mlp2_w2 = (const float*)d_in[11];
    float* out = (float*)d_out;

    repack_wqkv<<<(8 * 224 * 84 + 255) / 256, 256>>>(w_qk, w_v);

    cudaFuncSetAttribute(fa_window_kernel,
                         cudaFuncAttributeMaxDynamicSharedMemorySize,
                         FA_SMEM_BYTES);
    fa_window_kernel<<<4096, 256, FA_SMEM_BYTES>>>(
        x, w_out, b_out, pcq_w, pcq_b, pck_w, pck_b,
        mlp1_w, mlp2_w1, mlp2_w2, out);
}